// round 7
// baseline (speedup 1.0000x reference)
#include <cuda_runtime.h>
#include <math.h>

#define RING 256
#define DD   128
#define SD   42
#define G3   126
#define BB   512
#define TT   512
#define NCLS 1000
#define INPD 64
#define PBA  4        // batches per CTA in phase A
#define PBB  8        // batches per CTA in phase B

// static device scratch (no runtime allocation)
__device__ float g_gx[(size_t)BB * TT * G3];     // 132 MB gate inputs
__device__ float g_u [(size_t)BB * TT * DD];     // 134 MB write vectors
__device__ float g_jg[(size_t)BB * TT * 8];      // 8.4 MB per-warp ju/gu partials
__device__ float g_wct[INPD * 128];
__device__ float g_cc[128];
__device__ int   g_hidx[(size_t)BB * TT];
__device__ float g_hcoef[(size_t)BB * TT];
__device__ int   g_hcnt[BB];

// ---------------- packed f32x2 helpers ----------------
__device__ __forceinline__ unsigned long long pack2(float a, float b) {
    unsigned long long r; asm("mov.b64 %0,{%1,%2};" : "=l"(r) : "f"(a), "f"(b)); return r;
}
__device__ __forceinline__ void fma2(unsigned long long& acc, unsigned long long a, unsigned long long b) {
    asm("fma.rn.f32x2 %0,%1,%2,%0;" : "+l"(acc) : "l"(a), "l"(b));
}
__device__ __forceinline__ float unpack_sum(unsigned long long a) {
    float lo, hi; asm("mov.b64 {%0,%1},%2;" : "=f"(lo), "=f"(hi) : "l"(a)); return lo + hi;
}

// accurate math (R1/R5 recipe: rel_err ~1e-6)
__device__ __forceinline__ float sigm(float x) { return 1.0f / (1.0f + __expf(-x)); }

// exact 5-tap Gaussian softmax window
__device__ __forceinline__ void ringkern(float p, int* pos, float* wn) {
    float base = floorf(p);
    float frac = p - base;
    int ib = (int)base;
    float e[5]; float s = 0.f;
#pragma unroll
    for (int k = 0; k < 5; k++) {
        pos[k] = (ib + k - 2 + RING) & (RING - 1);
        float d = (float)(k - 2) - frac;
        e[k] = __expf(d * d * (-0.125f));
        s += e[k];
    }
    float inv = 1.0f / s;
#pragma unroll
    for (int k = 0; k < 5; k++) wn[k] = e[k] * inv;
}

// exact wrap to [0,256) for x in (-256, 512): bitwise-identical to fmodf+fixup here
__device__ __forceinline__ float wrap256(float x) {
    if (x >= 256.f) x -= 256.f;
    if (x < 0.f)    x += 256.f;
    return x;
}

// ---------------------------------------------------------------------------
// Kernel 0: fuse w_ih@w_proj -> g_wct, g_cc
// ---------------------------------------------------------------------------
__global__ void prep_kernel(const float* __restrict__ w_ih, const float* __restrict__ w_proj,
                            const float* __restrict__ b_ih, const float* __restrict__ b_proj) {
    int tid = blockIdx.x * blockDim.x + threadIdx.x;
    int nt  = gridDim.x * blockDim.x;
    for (int idx = tid; idx < INPD * 128; idx += nt) {
        int i = idx >> 7, j = idx & 127;
        float acc = 0.f;
        if (j < G3)
            for (int k = 0; k < SD; k++)
                acc = fmaf(w_ih[j * SD + k], w_proj[k * INPD + i], acc);
        g_wct[idx] = acc;
    }
    for (int j = tid; j < 128; j += nt) {
        float acc = 0.f;
        if (j < G3) {
            acc = b_ih[j];
            for (int k = 0; k < SD; k++) acc = fmaf(w_ih[j * SD + k], b_proj[k], acc);
        }
        g_cc[j] = acc;
    }
}

// ---------------------------------------------------------------------------
// Kernel 1: gx = x @ Wct + cc  (32 rows/block, 40.7 KB smem)
// ---------------------------------------------------------------------------
__global__ __launch_bounds__(256, 2) void gx_kernel(const float* __restrict__ x) {
    __shared__ float xs[32 * INPD];
    __shared__ __align__(16) float wcs[INPD * 128];
    __shared__ float ccs[128];
    int tid = threadIdx.x;
    size_t row0 = (size_t)blockIdx.x * 32;

    for (int i = tid; i < 32 * INPD; i += 256) xs[i] = x[row0 * INPD + i];
    for (int i = tid; i < INPD * 128; i += 256) wcs[i] = g_wct[i];
    if (tid < 128) ccs[tid] = g_cc[tid];
    __syncthreads();

    int r  = tid >> 3;
    int jg = (tid & 7) << 4;

    unsigned long long acc[8];
#pragma unroll
    for (int q = 0; q < 8; q++)
        acc[q] = pack2(ccs[jg + 2 * q], ccs[jg + 2 * q + 1]);

#pragma unroll 8
    for (int i = 0; i < INPD; i++) {
        float xv = xs[r * INPD + i];
        unsigned long long xp = pack2(xv, xv);
        const ulonglong2* wr = (const ulonglong2*)&wcs[i * 128 + jg];
#pragma unroll
        for (int q2 = 0; q2 < 4; q2++) {
            ulonglong2 w2 = wr[q2];
            fma2(acc[2 * q2],     xp, w2.x);
            fma2(acc[2 * q2 + 1], xp, w2.y);
        }
    }
    float* o0 = &g_gx[(row0 + r) * (size_t)G3];
#pragma unroll
    for (int q = 0; q < 8; q++) {
        float lo, hi;
        asm("mov.b64 {%0,%1},%2;" : "=f"(lo), "=f"(hi) : "l"(acc[q]));
        int j = jg + 2 * q;
        if (j < G3)     o0[j]     = lo;
        if (j + 1 < G3) o0[j + 1] = hi;
    }
}

// ---------------------------------------------------------------------------
// Kernel 2 (phase A): h/u recurrence, 4 batches per CTA (ILP over the serial
// chain). 128 CTAs x 128 threads; weights in smem (pair layout, conflict-free),
// fp order bitwise-identical to the 1-batch version.
// ---------------------------------------------------------------------------
__global__ __launch_bounds__(128) void phaseA_kernel(
    const float* __restrict__ w_hh, const float* __restrict__ b_hh,
    const float* __restrict__ w_bridge, const float* __restrict__ b_bridge,
    const float* __restrict__ w_jump, const float* __restrict__ w_gate)
{
    __shared__ unsigned long long whh2[21 * 128];          // [p][tid] pairs
    __shared__ unsigned long long wbr2[21 * 128];
    __shared__ __align__(16) float h_s[PBA][48];
    __shared__ float gh_s[PBA * 128];

    const int tid  = threadIdx.x;
    const int lane = tid & 31;
    const int wid  = tid >> 5;
    const int b0   = blockIdx.x * PBA;

    for (int idx = tid; idx < 21 * 128; idx += 128) {
        int p = idx >> 7, j = idx & 127;
        whh2[idx] = (j < G3) ? pack2(w_hh[j * SD + 2 * p], w_hh[j * SD + 2 * p + 1]) : 0ull;
        wbr2[idx] = pack2(w_bridge[j * SD + 2 * p], w_bridge[j * SD + 2 * p + 1]);
    }
    if (tid < 48) {
#pragma unroll
        for (int bb = 0; bb < PBA; bb++) h_s[bb][tid] = 0.f;
    }

    const float bhh = (tid < G3) ? b_hh[tid] : 0.f;
    const float bbr = b_bridge[tid];
    const float wj  = w_jump[tid];
    const float wg  = w_gate[tid];

    // prefetch gx for t=0,1 (double buffer), threads < SD only
    float a0[PBA], a1[PBA], a2[PBA], c0[PBA], c1[PBA], c2[PBA];
#pragma unroll
    for (int bb = 0; bb < PBA; bb++) { a0[bb]=a1[bb]=a2[bb]=c0[bb]=c1[bb]=c2[bb]=0.f; }
    if (tid < SD) {
#pragma unroll
        for (int bb = 0; bb < PBA; bb++) {
            const float* gx = g_gx + (size_t)(b0 + bb) * TT * G3;
            a0[bb] = __ldcs(gx + tid);      a1[bb] = __ldcs(gx + SD + tid);      a2[bb] = __ldcs(gx + 2 * SD + tid);
            c0[bb] = __ldcs(gx + G3 + tid); c1[bb] = __ldcs(gx + G3 + SD + tid); c2[bb] = __ldcs(gx + G3 + 2 * SD + tid);
        }
    }
    __syncthreads();

    for (int i = 0; i <= TT; i++) {
        // ---- R phase: merged gh/u dots over shared h loads ----
        unsigned long long ga0[PBA], ga1[PBA], ua0[PBA], ua1[PBA];
#pragma unroll
        for (int bb = 0; bb < PBA; bb++) { ga0[bb]=ga1[bb]=ua0[bb]=ua1[bb]=0ull; }
#pragma unroll
        for (int q = 0; q < 10; q++) {
            unsigned long long wh0 = whh2[(2 * q) * 128 + tid];
            unsigned long long wh1 = whh2[(2 * q + 1) * 128 + tid];
            unsigned long long wb0 = wbr2[(2 * q) * 128 + tid];
            unsigned long long wb1 = wbr2[(2 * q + 1) * 128 + tid];
#pragma unroll
            for (int bb = 0; bb < PBA; bb++) {
                ulonglong2 hh = ((const ulonglong2*)h_s[bb])[q];
                fma2(ga0[bb], wh0, hh.x);
                fma2(ga1[bb], wh1, hh.y);
                fma2(ua0[bb], wb0, hh.x);
                fma2(ua1[bb], wb1, hh.y);
            }
        }
        {
            unsigned long long wh20 = whh2[20 * 128 + tid];
            unsigned long long wb20 = wbr2[20 * 128 + tid];
#pragma unroll
            for (int bb = 0; bb < PBA; bb++) {
                unsigned long long hp20 = ((const unsigned long long*)h_s[bb])[20];
                fma2(ga0[bb], wh20, hp20);
                fma2(ua0[bb], wb20, hp20);
            }
        }
#pragma unroll
        for (int bb = 0; bb < PBA; bb++)
            gh_s[bb * 128 + tid] = unpack_sum(ga0[bb]) + unpack_sum(ga1[bb]) + bhh;
        __syncthreads();                                  // B1

        // ---- W phase: GRU (threads<SD) || u finalize + reductions (all) ----
        if (i < TT && tid < SD) {
#pragma unroll
            for (int bb = 0; bb < PBA; bb++) {
                float rg = sigm(a0[bb] + gh_s[bb * 128 + tid]);
                float zg = sigm(a1[bb] + gh_s[bb * 128 + SD + tid]);
                float ng = tanhf(a2[bb] + rg * gh_s[bb * 128 + 2 * SD + tid]);
                h_s[bb][tid] = (1.f - zg) * ng + zg * h_s[bb][tid];
            }
            // rotate prefetch buffers; fetch step i+2
            int tn = (i + 2 < TT) ? i + 2 : TT - 1;
#pragma unroll
            for (int bb = 0; bb < PBA; bb++) {
                a0[bb] = c0[bb]; a1[bb] = c1[bb]; a2[bb] = c2[bb];
                const float* gp2 = g_gx + ((size_t)(b0 + bb) * TT + tn) * G3;
                c0[bb] = __ldcs(gp2 + tid);
                c1[bb] = __ldcs(gp2 + SD + tid);
                c2[bb] = __ldcs(gp2 + 2 * SD + tid);
            }
        }
        if (i > 0) {
#pragma unroll
            for (int bb = 0; bb < PBA; bb++) {
                float u = tanhf(unpack_sum(ua0[bb]) + unpack_sum(ua1[bb]) + bbr);
                __stcs(g_u + ((size_t)(b0 + bb) * TT + (i - 1)) * DD + tid, u);
                float jp = wj * u, gp = wg * u;
#pragma unroll
                for (int o = 16; o > 0; o >>= 1) {
                    jp += __shfl_xor_sync(0xffffffffu, jp, o);
                    gp += __shfl_xor_sync(0xffffffffu, gp, o);
                }
                if (lane == 0) {
                    float* jgp = g_jg + ((size_t)(b0 + bb) * TT + (i - 1)) * 8;
                    jgp[wid]     = jp;
                    jgp[4 + wid] = gp;
                }
            }
        }
        __syncthreads();                                  // B2
    }
}

// ---------------------------------------------------------------------------
// Kernel 3 (phase B): pointer scan, 1 thread/batch (8 per 32-thread CTA).
// ---------------------------------------------------------------------------
__global__ __launch_bounds__(32, 1) void phaseB_kernel(
    const float* __restrict__ b_jump, const float* __restrict__ b_gate,
    const float* __restrict__ theta)
{
    __shared__ float J_s[PBB][257];
    __shared__ float G_s[PBB][257];
    __shared__ float hist[PBB][TT];

    const int tid = threadIdx.x;
    for (int i = tid; i < PBB * 257; i += 32) {
        ((float*)J_s)[i] = 0.f;
        ((float*)G_s)[i] = 0.f;
    }
    __syncthreads();

    if (tid >= PBB) return;
    const int b = blockIdx.x * PBB + tid;

    float bj = b_jump[0], bg = b_gate[0];
    float ptr = fmodf(theta[0], 256.f);
    if (ptr < 0.f) ptr += 256.f;

    float* J = J_s[tid];
    float* G = G_s[tid];
    float* H = hist[tid];
    const float* jgp = g_jg + (size_t)b * TT * 8;

    for (int t = 0; t < TT; t++) {
        float4 pj = *(const float4*)(jgp + (size_t)t * 8);
        float4 pg = *(const float4*)(jgp + (size_t)t * 8 + 4);
        float ju = (pj.x + pj.y) + (pj.z + pj.w);
        float gu = (pg.x + pg.y) + (pg.z + pg.w);

        int pos[5]; float wn[5];
        ringkern(ptr, pos, wn);
        float jd = bj, gd = bg;
#pragma unroll
        for (int k = 0; k < 5; k++) {
            jd = fmaf(wn[k], J[pos[k]], jd);
            gd = fmaf(wn[k], G[pos[k]], gd);
        }
        float jump = sigm(jd) * 256.f;
        float gate = sigm(gd);
        float dlt = wrap256(jump - ptr + 128.f) - 128.f;
        ptr = wrap256(ptr + gate * dlt);
        H[t] = ptr;

        int pos2[5]; float wn2[5];
        ringkern(ptr, pos2, wn2);
#pragma unroll
        for (int k = 0; k < 5; k++) {
            J[pos2[k]] += wn2[k] * ju;
            G[pos2[k]] += wn2[k] * gu;
        }
    }

    // hit list for the final soft read
    float pF = H[TT - 1];
    int posf[5]; float wnf[5];
    ringkern(pF, posf, wnf);
    int ib_f = (int)floorf(pF);
    int cnt = 0;
    int*   hix = g_hidx  + (size_t)b * TT;
    float* hcf = g_hcoef + (size_t)b * TT;
    for (int t = 0; t < TT; t++) {
        float pt = H[t];
        int ib_t = (int)floorf(pt);
        int dw = ((ib_t - ib_f + 128) & 255) - 128;
        if (dw > -5 && dw < 5) {
            int pd[5]; float wn2[5];
            ringkern(pt, pd, wn2);
            float coef = 0.f;
#pragma unroll
            for (int k = 0; k < 5; k++) {
                int m = k + dw;
                if (m >= 0 && m < 5) coef = fmaf(wnf[m], wn2[k], coef);
            }
            hix[cnt] = t;
            hcf[cnt] = coef;
            cnt++;
        }
    }
    g_hcnt[b] = cnt;
}

// ---------------------------------------------------------------------------
// Kernel 4: final read + classifier. 1 CTA/batch.
// ---------------------------------------------------------------------------
__global__ __launch_bounds__(128) void final_kernel(
    const float* __restrict__ w_cls, const float* __restrict__ b_cls,
    float* __restrict__ out)
{
    __shared__ int   idx_s[TT];
    __shared__ float cf_s[TT];
    __shared__ float r_s[128];

    const int tid = threadIdx.x;
    const int b   = blockIdx.x;

    int cnt = g_hcnt[b];
    for (int i = tid; i < cnt; i += 128) {
        idx_s[i] = g_hidx[(size_t)b * TT + i];
        cf_s[i]  = g_hcoef[(size_t)b * TT + i];
    }
    __syncthreads();

    const float* up = g_u + (size_t)b * TT * DD;
    float rf = 0.f;
    for (int i = 0; i < cnt; i++)
        rf = fmaf(cf_s[i], __ldcg(up + (size_t)idx_s[i] * DD + tid), rf);
    r_s[tid] = rf;
    __syncthreads();

    for (int n = tid; n < NCLS; n += 128) {
        float acc = b_cls[n];
        const float4* wr = (const float4*)(w_cls + (size_t)n * DD);
#pragma unroll 8
        for (int q = 0; q < 32; q++) {
            float4 w4 = wr[q];
            acc = fmaf(r_s[q * 4 + 0], w4.x, acc);
            acc = fmaf(r_s[q * 4 + 1], w4.y, acc);
            acc = fmaf(r_s[q * 4 + 2], w4.z, acc);
            acc = fmaf(r_s[q * 4 + 3], w4.w, acc);
        }
        out[(size_t)b * NCLS + n] = acc;
    }
}

// ---------------------------------------------------------------------------
extern "C" void kernel_launch(void* const* d_in, const int* in_sizes, int n_in,
                              void* d_out, int out_size) {
    const float* x        = (const float*)d_in[0];
    const float* theta    = (const float*)d_in[1];
    const float* w_proj   = (const float*)d_in[2];
    const float* b_proj   = (const float*)d_in[3];
    const float* w_ih     = (const float*)d_in[4];
    const float* w_hh     = (const float*)d_in[5];
    const float* b_ih     = (const float*)d_in[6];
    const float* b_hh     = (const float*)d_in[7];
    const float* w_bridge = (const float*)d_in[8];
    const float* b_bridge = (const float*)d_in[9];
    const float* w_jump   = (const float*)d_in[10];
    const float* b_jump   = (const float*)d_in[11];
    const float* w_gate   = (const float*)d_in[12];
    const float* b_gate   = (const float*)d_in[13];
    const float* w_cls    = (const float*)d_in[14];
    const float* b_cls    = (const float*)d_in[15];
    float* out = (float*)d_out;

    prep_kernel<<<16, 256>>>(w_ih, w_proj, b_ih, b_proj);
    gx_kernel<<<(BB * TT) / 32, 256>>>(x);
    phaseA_kernel<<<BB / PBA, 128>>>(w_hh, b_hh, w_bridge, b_bridge, w_jump, w_gate);
    phaseB_kernel<<<BB / PBB, 32>>>(b_jump, b_gate, theta);
    final_kernel<<<BB, 128>>>(w_cls, b_cls, out);
}